// round 1
// baseline (speedup 1.0000x reference)
#include <cuda_runtime.h>

// LSTM scan: T=2048, B=4096, IN_S=1, H=20, OUT_S=1, no biases.
// gates (PyTorch order i,f,g,o): gates = u*W_ih^T + h @ W_hh^T
// Thread layout: 20 threads per batch element (one per H index k), each thread
// computes all 4 gate preactivations for its k (4 dots of length 20, weights in
// registers), then c,h locally. h exchanged via double-buffered SMEM, one
// __syncthreads per step. u staged per 64-step chunk; y staged and flushed.

#define TSTEPS 2048
#define BATCH  4096
#define H      20
#define BPB    8            // batch elements per block
#define TPB    (BPB * H)    // 160 threads
#define CHUNK  64
#define NBLK   (BATCH / BPB)  // 512 blocks

__device__ __forceinline__ float sigf(float x) {
    // 1/(1+exp(-x)) via MUFU EX2 + MUFU RCP, rel err ~1e-6
    return __fdividef(1.0f, 1.0f + __expf(-x));
}

__device__ __forceinline__ float tanh_f(float x) {
    // tanh(x) = 1 - 2/(exp(2x)+1); saturates correctly at +-inf
    return 1.0f - __fdividef(2.0f, __expf(2.0f * x) + 1.0f);
}

__global__ void __launch_bounds__(TPB, 3)
lstm_scan_kernel(const float* __restrict__ u,     // [T, B, 1]
                 const float* __restrict__ Wih,   // [80, 1]
                 const float* __restrict__ Whh,   // [80, 20]
                 const float* __restrict__ Wout,  // [1, 20]
                 float* __restrict__ out)         // [T, B, 1]
{
    __shared__ __align__(16) float h_sh[2][BPB][H];   // double-buffered hidden state
    __shared__ float u_sh[CHUNK][BPB];
    __shared__ float y_sh[CHUNK][BPB];
    __shared__ float wout_sh[H];

    const int tid = threadIdx.x;
    const int bl  = tid / H;     // local batch index 0..7
    const int k   = tid % H;     // H index 0..19
    const int b0  = blockIdx.x * BPB;

    // Per-thread weights: rows (g*20 + k) of W_hh for g = 0..3  (80 registers)
    float w[4][H];
    float wih[4];
#pragma unroll
    for (int g = 0; g < 4; g++) {
        wih[g] = Wih[g * H + k];
#pragma unroll
        for (int j = 0; j < H; j++)
            w[g][j] = Whh[(g * H + k) * H + j];
    }
    if (tid < H) wout_sh[tid] = Wout[tid];

    h_sh[0][bl][k] = 0.0f;   // h0 = 0
    float c = 0.0f;          // c0 = 0
    int pb = 0;              // buffer holding h_{t-1}

#pragma unroll 1
    for (int tc = 0; tc < TSTEPS / CHUNK; tc++) {
        __syncthreads();  // prev chunk's y_sh writes complete; u_sh reads done

        // Flush y of previous chunk (coalesced-ish STG)
        if (tc > 0) {
            const int t0p = (tc - 1) * CHUNK;
#pragma unroll 1
            for (int e = tid; e < CHUNK * BPB; e += TPB) {
                const int r = e / BPB, cc = e % BPB;
                out[(t0p + r) * BATCH + b0 + cc] = y_sh[r][cc];
            }
        }
        // Stage this chunk of u into SMEM
        {
            const int t0 = tc * CHUNK;
#pragma unroll 1
            for (int e = tid; e < CHUNK * BPB; e += TPB) {
                const int r = e / BPB, cc = e % BPB;
                u_sh[r][cc] = u[(t0 + r) * BATCH + b0 + cc];
            }
        }
        __syncthreads();

#pragma unroll 1
        for (int tt = 0; tt < CHUNK; tt++) {
            // Load h_{t-1} for my batch element (LDS128 broadcasts)
            float hv[H];
#pragma unroll
            for (int q = 0; q < H / 4; q++) {
                float4 v = *reinterpret_cast<const float4*>(&h_sh[pb][bl][q * 4]);
                hv[q * 4 + 0] = v.x;
                hv[q * 4 + 1] = v.y;
                hv[q * 4 + 2] = v.z;
                hv[q * 4 + 3] = v.w;
            }
            const float x = u_sh[tt][bl];

            float ai = x * wih[0];
            float af = x * wih[1];
            float ag = x * wih[2];
            float ao = x * wih[3];
#pragma unroll
            for (int j = 0; j < H; j++) {
                ai = fmaf(hv[j], w[0][j], ai);
                af = fmaf(hv[j], w[1][j], af);
                ag = fmaf(hv[j], w[2][j], ag);
                ao = fmaf(hv[j], w[3][j], ao);
            }
            const float ig = sigf(ai);
            const float fg = sigf(af);
            const float gg = tanh_f(ag);
            const float og = sigf(ao);
            c = fg * c + ig * gg;
            const float h = og * tanh_f(c);

            h_sh[pb ^ 1][bl][k] = h;
            __syncthreads();

            // One thread per batch element computes y_t = h_t . w_out
            if (k == 0) {
                float y = 0.0f;
#pragma unroll
                for (int j = 0; j < H; j++)
                    y = fmaf(h_sh[pb ^ 1][bl][j], wout_sh[j], y);
                y_sh[tt][bl] = y;
            }
            pb ^= 1;
        }
    }

    // Final chunk flush
    __syncthreads();
    {
        const int t0p = (TSTEPS / CHUNK - 1) * CHUNK;
#pragma unroll 1
        for (int e = tid; e < CHUNK * BPB; e += TPB) {
            const int r = e / BPB, cc = e % BPB;
            out[(t0p + r) * BATCH + b0 + cc] = y_sh[r][cc];
        }
    }
}

extern "C" void kernel_launch(void* const* d_in, const int* in_sizes, int n_in,
                              void* d_out, int out_size) {
    const float* u    = (const float*)d_in[0];  // [2048, 4096, 1]
    const float* Wih  = (const float*)d_in[1];  // [80, 1]
    const float* Whh  = (const float*)d_in[2];  // [80, 20]
    const float* Wout = (const float*)d_in[3];  // [1, 20]
    float* out = (float*)d_out;                 // [2048, 4096, 1]

    lstm_scan_kernel<<<NBLK, TPB>>>(u, Wih, Whh, Wout, out);
}